// round 12
// baseline (speedup 1.0000x reference)
#include <cuda_runtime.h>
#include <math.h>

#define NN 100000
#define DD 128
#define OO 128
#define VV 3
#define EE 400000
#define RT 132
#define NBLK 782
#define NT 256
#define TILEF (128 * RT)
#define WQF 8192
#define SMEMF (TILEF + WQF + 160)
#define SMEM_BYTES (SMEMF * 4)

typedef unsigned long long u64;

// ---------------- device scratch ----------------
__device__ float g_X[VV * NN * DD];
__device__ float g_s[VV * NN];
__device__ float g_att[NN];
__device__ float g_sfus[NN * OO];
__device__ float g_trans[NN * OO];
__device__ float g_views[VV * NN * OO];
__device__ float g_vscore[VV * NN];
__device__ float g_wp[OO * OO];
__device__ float g_bp[OO];

// ---------------- f32x2 helpers ----------------
__device__ __forceinline__ u64 pack2(float x, float y) {
    u64 r; asm("mov.b64 %0, {%1,%2};" : "=l"(r) : "f"(x), "f"(y)); return r;
}
__device__ __forceinline__ float2 unpack2(u64 v) {
    float2 f; asm("mov.b64 {%0,%1}, %2;" : "=f"(f.x), "=f"(f.y) : "l"(v)); return f;
}
__device__ __forceinline__ u64 fma2(u64 a, u64 b, u64 c) {
    u64 d; asm("fma.rn.f32x2 %0, %1, %2, %3;" : "=l"(d) : "l"(a), "l"(b), "l"(c)); return d;
}
__device__ __forceinline__ float sigm(float x) { return 1.0f / (1.0f + expf(-x)); }
__device__ __forceinline__ int nodeOf(int ng, int j) { return 4 * ng + (j < 4 ? j : 60 + j); }

#define CPCOMMIT asm volatile("cp.async.commit_group;" ::: "memory")

__device__ __forceinline__ void cpa16(float* ds, const float* gs) {
    unsigned sa = (unsigned)__cvta_generic_to_shared(ds);
    asm volatile("cp.async.ca.shared.global [%0], [%1], 16;" :: "r"(sa), "l"(gs) : "memory");
}
__device__ __forceinline__ void prefQ(float* dst, const float* __restrict__ src, int t) {
#pragma unroll
    for (int i = 0; i < 4; i++) cpa16(dst + 4 * (t + 256 * i), src + 4 * (t + 256 * i));
}
__device__ __forceinline__ void gemm_pre(float* wq, const float* __restrict__ wsrc, int t) {
    prefQ(wq, wsrc, t); CPCOMMIT;
    prefQ(wq + 4096, wsrc + 4096, t); CPCOMMIT;
}

// ---------------- loaders (SW-templated) ----------------
template <int SW>
__device__ __forceinline__ void load_tileT(float* dst, const float* __restrict__ src,
                                           int nb, int t) {
    for (int idx = t; idx < 4096; idx += NT) {
        int nodeLow = idx & 31;
        int kq = (idx >> 5) & 31;
        int node = ((idx >> 10) << 5) + nodeLow;
        float4 val = make_float4(0.f, 0.f, 0.f, 0.f);
        if (nb + node < NN) val = ((const float4*)src)[(size_t)(nb + node) * 32 + kq];
        int nc = SW ? (node ^ (((kq >> 1) & 7) << 2)) : node;
        dst[(4 * kq + 0) * RT + nc] = val.x;
        dst[(4 * kq + 1) * RT + nc] = val.y;
        dst[(4 * kq + 2) * RT + nc] = val.z;
        dst[(4 * kq + 3) * RT + nc] = val.w;
    }
}
__device__ __forceinline__ void load_la(float* wb, const float* __restrict__ la_w1,
                                        int half, int t) {
    for (int i = t; i < 2048; i += NT) {
        int d = i >> 5, col4 = i & 31;
        int c = col4 >> 4, h4 = col4 & 15;
        ((float4*)wb)[d * 32 + col4] =
            ((const float4*)la_w1)[(size_t)c * 2048 + (d + 64 * half) * 16 + h4];
    }
}

// ---------------- 8x8 register-tiled GEMM core ----------------
template <int KK, int WS, int SW>
__device__ __forceinline__ void mmTile(const float* __restrict__ tile, int baseRow,
                                       int colbase, const float* __restrict__ wp,
                                       u64* acc) {
#pragma unroll
    for (int g = 0; g < KK / 8; g++) {
        const float* aT = tile + (baseRow + 8 * g) * RT
                        + (SW ? (colbase ^ ((((baseRow >> 3) + g) & 7) << 2)) : colbase);
#pragma unroll
        for (int kk = 0; kk < 8; kk++) {
            float4 x = *(const float4*)(aT);
            float4 y = *(const float4*)(aT + 64);
            float4 u = *(const float4*)(wp);
            float4 v = *(const float4*)(wp + 4);
            aT += RT; wp += WS;
            u64 p0 = pack2(x.x, x.y), p1 = pack2(x.z, x.w);
            u64 p2 = pack2(y.x, y.y), p3 = pack2(y.z, y.w);
            float wv[8] = {u.x, u.y, u.z, u.w, v.x, v.y, v.z, v.w};
#pragma unroll
            for (int n = 0; n < 8; n++) {
                u64 ws = pack2(wv[n], wv[n]);
                acc[n]      = fma2(p0, ws, acc[n]);
                acc[8 + n]  = fma2(p1, ws, acc[8 + n]);
                acc[16 + n] = fma2(p2, ws, acc[16 + n]);
                acc[24 + n] = fma2(p3, ws, acc[24 + n]);
            }
        }
    }
}

template <int SW>
__device__ __forceinline__ void gemm128p(const float* sfT, const float* __restrict__ wsrc,
                                         float* wq, int t, int og, int ng, u64* acc) {
#pragma unroll
    for (int c = 0; c < 4; c++) {
        if (c < 3) { asm volatile("cp.async.wait_group 1;" ::: "memory"); }
        else       { asm volatile("cp.async.wait_group 0;" ::: "memory"); }
        __syncthreads();
        mmTile<32, 128, SW>(sfT, 32 * c, 4 * ng, wq + (c & 1) * 4096 + 8 * og, acc);
        __syncthreads();
        if (c < 2) { prefQ(wq + (c & 1) * 4096, wsrc + (c + 2) * 4096, t); CPCOMMIT; }
    }
}

__device__ __forceinline__ void initB(u64* acc, const float* __restrict__ bias, int og) {
    float4 b0 = *(const float4*)(bias + 8 * og);
    float4 b1 = *(const float4*)(bias + 8 * og + 4);
    float bv[8] = {b0.x, b0.y, b0.z, b0.w, b1.x, b1.y, b1.z, b1.w};
#pragma unroll
    for (int n = 0; n < 8; n++) {
        u64 p = pack2(bv[n], bv[n]);
        acc[n] = p; acc[8 + n] = p; acc[16 + n] = p; acc[24 + n] = p;
    }
}

template <int SW>
__device__ __forceinline__ void storeT(float* tile, int og, int ng, const u64* acc) {
    float* b = tile + (SW ? ((4 * ng) ^ ((og & 7) << 2)) : (4 * ng));
#pragma unroll
    for (int n = 0; n < 8; n++) {
        float2 a0 = unpack2(acc[n]), a1 = unpack2(acc[8 + n]);
        float2 a2 = unpack2(acc[16 + n]), a3 = unpack2(acc[24 + n]);
        float* row = b + (8 * og + n) * RT;
        *(float4*)(row)      = make_float4(a0.x, a0.y, a1.x, a1.y);
        *(float4*)(row + 64) = make_float4(a2.x, a2.y, a3.x, a3.y);
    }
}

__device__ __forceinline__ void storeG(float* g, int nb, int og, int ng, const u64* acc) {
#pragma unroll
    for (int mp = 0; mp < 4; mp++) {
        int b = 4 * ng + (mp >> 1) * 64 + 2 * (mp & 1);
        int n0 = nb + b, n1 = n0 + 1;
        float2 c[8];
#pragma unroll
        for (int n = 0; n < 8; n++) c[n] = unpack2(acc[8 * mp + n]);
        if (n0 < NN) {
            float* p = g + (size_t)n0 * OO + 8 * og;
            *(float4*)p       = make_float4(c[0].x, c[1].x, c[2].x, c[3].x);
            *(float4*)(p + 4) = make_float4(c[4].x, c[5].x, c[6].x, c[7].x);
        }
        if (n1 < NN) {
            float* p = g + (size_t)n1 * OO + 8 * og;
            *(float4*)p       = make_float4(c[0].y, c[1].y, c[2].y, c[3].y);
            *(float4*)(p + 4) = make_float4(c[4].y, c[5].y, c[6].y, c[7].y);
        }
    }
}

// =====================================================================
__global__ void k_zero() {
    size_t tid = (size_t)blockIdx.x * blockDim.x + threadIdx.x;
    size_t stride = (size_t)gridDim.x * blockDim.x;
    float4 z = make_float4(0.f, 0.f, 0.f, 0.f);
    float4* X = (float4*)g_X;
    size_t nx = (size_t)VV * NN * DD / 4;
    for (size_t i = tid; i < nx; i += stride) X[i] = z;
    float4* S = (float4*)g_s;
    for (size_t i = tid; i < VV * NN / 4; i += stride) S[i] = z;
}

// =====================================================================
__global__ void __launch_bounds__(128) k_prep(const float* __restrict__ sl_w,
                                              const float* __restrict__ sl_b,
                                              const float* __restrict__ fus_w) {
    __shared__ float row[128];
    const int i = blockIdx.x, j = threadIdx.x;
    row[j] = sl_w[i * 128 + j];
    __syncthreads();
    float acc = 0.f;
#pragma unroll 8
    for (int k = 0; k < 128; k++) acc += row[k] * __ldg(&fus_w[k * 128 + j]);
    g_wp[i * 128 + j] = acc;
    if (i == 0) {
        float accb = 0.f;
#pragma unroll 8
        for (int k = 0; k < 128; k++) accb += __ldg(&sl_b[k]) * __ldg(&fus_w[k * 128 + j]);
        g_bp[j] = accb;
    }
}

// =====================================================================
// K1: LA attention, trans, sfus' + fused edge scatter  (SW=0, R10 layout)
// =====================================================================
__global__ void __launch_bounds__(NT, 2) k_node(
    const float* __restrict__ feat,
    const float* __restrict__ la_w1, const float* __restrict__ la_b1,
    const float* __restrict__ la_w2, const float* __restrict__ la_b2,
    const float* __restrict__ pred_w, const float* __restrict__ pred_b,
    const float* __restrict__ att_bias,
    const float* __restrict__ ft_w, const float* __restrict__ ft_b,
    const int* __restrict__ ei, const float* __restrict__ ew,
    float* __restrict__ probs, int write_probs) {
    extern __shared__ float sm[];
    float* sfT = sm;
    float* wq  = sm + TILEF;
    float* pwd = sm + TILEF + WQF;
    const int t = threadIdx.x, nb = blockIdx.x * 128;
    const int og = t & 15, ng = t >> 4;

    load_tileT<0>(sfT, feat, nb, t);
    load_la(wq, la_w1, 0, t);
    if (t < 128) pwd[t] = __ldg(&pred_w[2 * t]) - __ldg(&pred_w[2 * t + 1]);
    __syncthreads();

    // ---- label-aware attention ----
    {
        u64 acc[32];
        initB(acc, la_b1, og);
        mmTile<64, 128, 0>(sfT, 0, 4 * ng, wq + 8 * og, acc);
        __syncthreads();
        load_la(wq, la_w1, 1, t);
        __syncthreads();
        mmTile<64, 128, 0>(sfT, 64, 4 * ng, wq + 8 * og, acc);
        __syncthreads();                 // wq readers retired
        gemm_pre(wq, ft_w, t);           // prefetch ft_w behind LA epilogue

        u64 lgd[4] = {0, 0, 0, 0};
        const float* ap = sfT + 8 * og * RT + 4 * ng;
#pragma unroll
        for (int kk = 0; kk < 8; kk++) {
            float pw = pwd[8 * og + kk];
            u64 pws = pack2(pw, pw);
            float4 x = *(const float4*)(ap);
            float4 y = *(const float4*)(ap + 64);
            ap += RT;
            lgd[0] = fma2(pack2(x.x, x.y), pws, lgd[0]);
            lgd[1] = fma2(pack2(x.z, x.w), pws, lgd[1]);
            lgd[2] = fma2(pack2(y.x, y.y), pws, lgd[2]);
            lgd[3] = fma2(pack2(y.z, y.w), pws, lgd[3]);
        }
        float lg[8];
#pragma unroll
        for (int mp = 0; mp < 4; mp++) {
            float2 f = unpack2(lgd[mp]);
            lg[2 * mp] = f.x; lg[2 * mp + 1] = f.y;
        }
#pragma unroll
        for (int s = 1; s < 16; s <<= 1)
#pragma unroll
            for (int j = 0; j < 8; j++) lg[j] += __shfl_xor_sync(0xffffffffu, lg[j], s);

        float dt[8];
        {
            u64 dp[4] = {0, 0, 0, 0};
#pragma unroll
            for (int n = 0; n < 8; n++) {
                float wvn = la_w2[8 * og + n];
                u64 ws = pack2(wvn, wvn);
#pragma unroll
                for (int mp = 0; mp < 4; mp++) {
                    float2 a = unpack2(acc[8 * mp + n]);
                    dp[mp] = fma2(pack2(fmaxf(a.x, 0.f), fmaxf(a.y, 0.f)), ws, dp[mp]);
                }
            }
#pragma unroll
            for (int mp = 0; mp < 4; mp++) {
                float2 f = unpack2(dp[mp]);
                dt[2 * mp] = f.x; dt[2 * mp + 1] = f.y;
            }
#pragma unroll
            for (int s = 1; s < 8; s <<= 1)
#pragma unroll
                for (int j = 0; j < 8; j++) dt[j] += __shfl_xor_sync(0xffffffffu, dt[j], s);
        }
        const int c = og >> 3;
        const float b2 = la_b2[c];
        const float ab = att_bias[0];
        const float pbd = pred_b[0] - pred_b[1];
#pragma unroll
        for (int j = 0; j < 8; j++) {
            float sc = sigm(dt[j] + b2);
            float so = __shfl_xor_sync(0xffffffffu, sc, 8);
            float p0 = sigm(lg[j] + pbd);
            float pown = (c == 0) ? p0 : 1.f - p0;
            float att = sc * pown + so * (1.f - pown) + ab;
            int node = nb + nodeOf(ng, j);
            if (og == 0 && node < NN) {
                g_att[node] = att;
                if (write_probs) {
                    probs[(size_t)node * 2]     = p0;
                    probs[(size_t)node * 2 + 1] = 1.f - p0;
                }
            }
        }
    }
    {   // trans = f@ft_w + ft_b
        u64 acc[32];
        initB(acc, ft_b, og);
        gemm128p<0>(sfT, ft_w, wq, t, og, ng, acc);
        gemm_pre(wq, g_wp, t);
        storeG(g_trans, nb, og, ng, acc);
    }
    {   // sfus = f@W' + b'
        u64 acc[32];
        initB(acc, g_bp, og);
        gemm128p<0>(sfT, g_wp, wq, t, og, ng, acc);
        storeG(g_sfus, nb, og, ng, acc);
    }

    // ---- fused edge scatter ----
    {
        const int lane = t & 31;
        for (int gw = blockIdx.x * 8 + (t >> 5); gw < VV * EE; gw += NBLK * 8) {
            int v = gw / EE;
            int e = gw - v * EE;
            int src = ei[(size_t)v * 2 * EE + e];
            int dst = ei[(size_t)v * 2 * EE + EE + e];
            float w = ew[(size_t)v * EE + e];
            float4 m = ((const float4*)feat)[(size_t)src * 32 + lane];
            float* X = g_X + ((size_t)v * NN + dst) * DD + lane * 4;
            asm volatile("red.global.add.v4.f32 [%0], {%1,%2,%3,%4};"
                         :: "l"(X), "f"(m.x * w), "f"(m.y * w), "f"(m.z * w), "f"(m.w * w)
                         : "memory");
            if (lane == 0) atomicAdd(&g_s[(size_t)v * NN + dst], w);
        }
    }
}

// =====================================================================
// K3: per-view agg -> gate -> view/pe -> vscore  (SW=1, swizzled)
// =====================================================================
__global__ void __launch_bounds__(NT, 2) k_view(
    const float* __restrict__ rel_w, const float* __restrict__ rel_b,
    const float* __restrict__ gate_w, const float* __restrict__ gate_b,
    const float* __restrict__ view_pref,
    const float* __restrict__ va_w1, const float* __restrict__ va_b1,
    const float* __restrict__ va_w2, const float* __restrict__ va_b2) {
    extern __shared__ float sm[];
    float* sfT = sm;
    float* wq  = sm + TILEF;
    const int t = threadIdx.x, nb = blockIdx.x * 128;
    const int v = blockIdx.y;
    const int og = t & 15, ng = t >> 4;

    gemm_pre(wq, rel_w + (size_t)v * DD * OO, t);
    load_tileT<1>(sfT, g_X + (size_t)v * NN * DD, nb, t);
    __syncthreads();

    u64 sp[4];
#pragma unroll
    for (int mp = 0; mp < 4; mp++) {
        int b = 4 * ng + (mp >> 1) * 64 + 2 * (mp & 1);
        int i0 = min(nb + b, NN - 1), i1 = min(nb + b + 1, NN - 1);
        sp[mp] = pack2(g_s[v * NN + i0], g_s[v * NN + i1]);
    }
    {   // agg = X@rel_w + rel_b*s -> overwrite tile
        u64 acc[32];
        float4 b0 = *(const float4*)(rel_b + v * OO + 8 * og);
        float4 b1 = *(const float4*)(rel_b + v * OO + 8 * og + 4);
        float bv[8] = {b0.x, b0.y, b0.z, b0.w, b1.x, b1.y, b1.z, b1.w};
        u64 z = 0ull;
#pragma unroll
        for (int n = 0; n < 8; n++) {
            u64 rbs = pack2(bv[n], bv[n]);
#pragma unroll
            for (int mp = 0; mp < 4; mp++) acc[8 * mp + n] = fma2(rbs, sp[mp], z);
        }
        gemm128p<1>(sfT, rel_w + (size_t)v * DD * OO, wq, t, og, ng, acc);
        gemm_pre(wq, gate_w + (size_t)v * OO * OO, t);
        storeT<1>(sfT, og, ng, acc);     // tile := agg
        __syncthreads();
    }
    {   // gate logits; epilogue reads own agg cells then writes pe
        u64 acc[32];
        initB(acc, gate_b + v * OO, og);
        gemm128p<1>(sfT, gate_w + (size_t)v * OO * OO, wq, t, og, ng, acc);
        gemm_pre(wq, va_w1, t);
        float4 p0f = *(const float4*)(view_pref + v * OO + 8 * og);
        float4 p1f = *(const float4*)(view_pref + v * OO + 8 * og + 4);
        float pv[8] = {p0f.x, p0f.y, p0f.z, p0f.w, p1f.x, p1f.y, p1f.z, p1f.w};
        const float* ab = sfT + ((4 * ng) ^ ((og & 7) << 2));
#pragma unroll
        for (int n = 0; n < 8; n++) {
            const float* arow = ab + (8 * og + n) * RT;
            float4 ga = *(const float4*)(arow);
            float4 gb = *(const float4*)(arow + 64);
            float2 a0 = unpack2(acc[n]),      a1 = unpack2(acc[8 + n]);
            float2 a2 = unpack2(acc[16 + n]), a3 = unpack2(acc[24 + n]);
            acc[n]      = pack2(sigm(a0.x) * ga.x, sigm(a0.y) * ga.y);
            acc[8 + n]  = pack2(sigm(a1.x) * ga.z, sigm(a1.y) * ga.w);
            acc[16 + n] = pack2(sigm(a2.x) * gb.x, sigm(a2.y) * gb.y);
            acc[24 + n] = pack2(sigm(a3.x) * gb.z, sigm(a3.y) * gb.w);
        }
        storeG(g_views + (size_t)v * NN * OO, nb, og, ng, acc);
        u64 z = 0ull;
#pragma unroll
        for (int n = 0; n < 8; n++) {
            u64 ps = pack2(pv[n], pv[n]);
#pragma unroll
            for (int mp = 0; mp < 4; mp++) acc[8 * mp + n] = fma2(acc[8 * mp + n], ps, z);
        }
        storeT<1>(sfT, og, ng, acc);     // tile := pe
    }
    asm volatile("cp.async.wait_group 0;" ::: "memory");
    __syncthreads();
    {   // vh = relu(pe@va_w1+b1); vscore (split-k over og bit3)
        const int ogp = og & 7, kh = og >> 3;
        u64 acc[32];
        if (kh == 0) {
            float4 b0 = *(const float4*)(va_b1 + 8 * ogp);
            float4 b1 = *(const float4*)(va_b1 + 8 * ogp + 4);
            float bv[8] = {b0.x, b0.y, b0.z, b0.w, b1.x, b1.y, b1.z, b1.w};
#pragma unroll
            for (int n = 0; n < 8; n++) {
                u64 p = pack2(bv[n], bv[n]);
                acc[n] = p; acc[8 + n] = p; acc[16 + n] = p; acc[24 + n] = p;
            }
        } else {
#pragma unroll
            for (int i = 0; i < 32; i++) acc[i] = 0ull;
        }
        mmTile<64, 64, 1>(sfT, 64 * kh, 4 * ng, wq + 4096 * kh + 8 * ogp, acc);
        float4 w0 = *(const float4*)(va_w2 + 8 * ogp);
        float4 w1 = *(const float4*)(va_w2 + 8 * ogp + 4);
        float wv[8] = {w0.x, w0.y, w0.z, w0.w, w1.x, w1.y, w1.z, w1.w};
        float dt[8] = {0.f, 0.f, 0.f, 0.f, 0.f, 0.f, 0.f, 0.f};
#pragma unroll
        for (int n = 0; n < 8; n++) {
            float wvn = wv[n];
#pragma unroll
            for (int mp = 0; mp < 4; mp++) {
                float2 a = unpack2(acc[8 * mp + n]);
                a.x += __shfl_xor_sync(0xffffffffu, a.x, 8);
                a.y += __shfl_xor_sync(0xffffffffu, a.y, 8);
                dt[2 * mp]     += fmaxf(a.x, 0.f) * wvn;
                dt[2 * mp + 1] += fmaxf(a.y, 0.f) * wvn;
            }
        }
#pragma unroll
        for (int s = 1; s < 8; s <<= 1)
#pragma unroll
            for (int j = 0; j < 8; j++) dt[j] += __shfl_xor_sync(0xffffffffu, dt[j], s);
        if (og == 0) {
            float vb = va_b2[0];
#pragma unroll
            for (int j = 0; j < 8; j++) {
                int node = nb + nodeOf(ng, j);
                if (node < NN) g_vscore[v * NN + node] = dt[j] + vb;
            }
        }
    }
}

// =====================================================================
// K4: softmax-combine, fuse, layernorm  (SW=0, R10 layout)
// =====================================================================
__global__ void __launch_bounds__(NT, 2) k_final(
    const float* __restrict__ fus_w_bot, const float* __restrict__ fus_b,
    const float* __restrict__ ln_g, const float* __restrict__ ln_beta,
    float* __restrict__ out) {
    extern __shared__ float sm[];
    float* sfT = sm;
    float* wq  = sm + TILEF;
    const int t = threadIdx.x, nb = blockIdx.x * 128;
    const int og = t & 15, ng = t >> 4;

    gemm_pre(wq, fus_w_bot, t);
#pragma unroll
    for (int j = 0; j < 8; j++) {
        int col = nodeOf(ng, j);
        int ncl = min(nb + col, NN - 1);
        float s0 = g_vscore[ncl], s1 = g_vscore[NN + ncl], s2 = g_vscore[2 * NN + ncl];
        float mx = fmaxf(s0, fmaxf(s1, s2));
        float e0 = expf(s0 - mx), e1 = expf(s1 - mx), e2 = expf(s2 - mx);
        float att = g_att[ncl] / (e0 + e1 + e2);
        float p0 = e0 * att, p1 = e1 * att, p2 = e2 * att;
        const float* v0 = g_views + (size_t)ncl * OO + 8 * og;
        const float* v1 = g_views + ((size_t)NN + ncl) * OO + 8 * og;
        const float* v2 = g_views + ((size_t)2 * NN + ncl) * OO + 8 * og;
        float4 a0 = *(const float4*)v0, a1 = *(const float4*)(v0 + 4);
        float4 b0 = *(const float4*)v1, b1 = *(const float4*)(v1 + 4);
        float4 c0 = *(const float4*)v2, c1 = *(const float4*)(v2 + 4);
        float w[8];
        w[0] = a0.x * p0 + b0.x * p1 + c0.x * p2;
        w[1] = a0.y * p0 + b0.y * p1 + c0.y * p2;
        w[2] = a0.z * p0 + b0.z * p1 + c0.z * p2;
        w[3] = a0.w * p0 + b0.w * p1 + c0.w * p2;
        w[4] = a1.x * p0 + b1.x * p1 + c1.x * p2;
        w[5] = a1.y * p0 + b1.y * p1 + c1.y * p2;
        w[6] = a1.z * p0 + b1.z * p1 + c1.z * p2;
        w[7] = a1.w * p0 + b1.w * p1 + c1.w * p2;
#pragma unroll
        for (int n = 0; n < 8; n++) sfT[(8 * og + n) * RT + col] = w[n];
    }
    __syncthreads();

    u64 acc[32];
    {
        float4 f0 = *(const float4*)(fus_b + 8 * og);
        float4 f1 = *(const float4*)(fus_b + 8 * og + 4);
        float bv[8] = {f0.x, f0.y, f0.z, f0.w, f1.x, f1.y, f1.z, f1.w};
#pragma unroll
        for (int mp = 0; mp < 4; mp++) {
            int b = 4 * ng + (mp >> 1) * 64 + 2 * (mp & 1);
            int i0 = min(nb + b, NN - 1), i1 = min(nb + b + 1, NN - 1);
            const float* s0p = g_sfus + (size_t)i0 * OO + 8 * og;
            const float* s1p = g_sfus + (size_t)i1 * OO + 8 * og;
            float4 s00 = *(const float4*)s0p, s01 = *(const float4*)(s0p + 4);
            float4 s10 = *(const float4*)s1p, s11 = *(const float4*)(s1p + 4);
            float sa[8] = {s00.x, s00.y, s00.z, s00.w, s01.x, s01.y, s01.z, s01.w};
            float sb[8] = {s10.x, s10.y, s10.z, s10.w, s11.x, s11.y, s11.z, s11.w};
#pragma unroll
            for (int n = 0; n < 8; n++)
                acc[8 * mp + n] = pack2(sa[n] + bv[n], sb[n] + bv[n]);
        }
    }
    gemm128p<0>(sfT, fus_w_bot, wq, t, og, ng, acc);

    float sums[8] = {0, 0, 0, 0, 0, 0, 0, 0};
    float sqs[8]  = {0, 0, 0, 0, 0, 0, 0, 0};
#pragma unroll
    for (int mp = 0; mp < 4; mp++) {
        int b = 4 * ng + (mp >> 1) * 64 + 2 * (mp & 1);
        int i0 = min(nb + b, NN - 1), i1 = min(nb + b + 1, NN - 1);
        const float* t0p = g_trans + (size_t)i0 * OO + 8 * og;
        const float* t1p = g_trans + (size_t)i1 * OO + 8 * og;
        float4 t00 = *(const float4*)t0p, t01 = *(const float4*)(t0p + 4);
        float4 t10 = *(const float4*)t1p, t11 = *(const float4*)(t1p + 4);
        float ta[8] = {t00.x, t00.y, t00.z, t00.w, t01.x, t01.y, t01.z, t01.w};
        float tb[8] = {t10.x, t10.y, t10.z, t10.w, t11.x, t11.y, t11.z, t11.w};
#pragma unroll
        for (int n = 0; n < 8; n++) {
            float2 a = unpack2(acc[8 * mp + n]);
            float o0 = fmaxf(a.x, 0.f) + ta[n];
            float o1 = fmaxf(a.y, 0.f) + tb[n];
            acc[8 * mp + n] = pack2(o0, o1);
            sums[2 * mp] += o0; sqs[2 * mp] += o0 * o0;
            sums[2 * mp + 1] += o1; sqs[2 * mp + 1] += o1 * o1;
        }
    }
#pragma unroll
    for (int s = 1; s < 16; s <<= 1)
#pragma unroll
        for (int j = 0; j < 8; j++) {
            sums[j] += __shfl_xor_sync(0xffffffffu, sums[j], s);
            sqs[j]  += __shfl_xor_sync(0xffffffffu, sqs[j], s);
        }
    float4 g0 = *(const float4*)(ln_g + 8 * og), g1 = *(const float4*)(ln_g + 8 * og + 4);
    float4 e0 = *(const float4*)(ln_beta + 8 * og), e1 = *(const float4*)(ln_beta + 8 * og + 4);
    float gv[8] = {g0.x, g0.y, g0.z, g0.w, g1.x, g1.y, g1.z, g1.w};
    float ev[8] = {e0.x, e0.y, e0.z, e0.w, e1.x, e1.y, e1.z, e1.w};
#pragma unroll
    for (int mp = 0; mp < 4; mp++) {
        int b = 4 * ng + (mp >> 1) * 64 + 2 * (mp & 1);
        int n0 = nb + b, n1 = n0 + 1;
        float mu0 = sums[2 * mp] * (1.f / 128.f);
        float mu1 = sums[2 * mp + 1] * (1.f / 128.f);
        float r0 = rsqrtf(sqs[2 * mp] * (1.f / 128.f) - mu0 * mu0 + 1e-5f);
        float r1 = rsqrtf(sqs[2 * mp + 1] * (1.f / 128.f) - mu1 * mu1 + 1e-5f);
        float2 c[8];
#pragma unroll
        for (int n = 0; n < 8; n++) c[n] = unpack2(acc[8 * mp + n]);
        if (n0 < NN) {
            float* p = out + (size_t)n0 * OO + 8 * og;
            float r[8];
#pragma unroll
            for (int n = 0; n < 8; n++) r[n] = (c[n].x - mu0) * r0 * gv[n] + ev[n];
            *(float4*)p       = make_float4(r[0], r[1], r[2], r[3]);
            *(float4*)(p + 4) = make_float4(r[4], r[5], r[6], r[7]);
        }
        if (n1 < NN) {
            float* p = out + (size_t)n1 * OO + 8 * og;
            float r[8];
#pragma unroll
            for (int n = 0; n < 8; n++) r[n] = (c[n].y - mu1) * r1 * gv[n] + ev[n];
            *(float4*)p       = make_float4(r[0], r[1], r[2], r[3]);
            *(float4*)(p + 4) = make_float4(r[4], r[5], r[6], r[7]);
        }
    }
}

// =====================================================================
extern "C" void kernel_launch(void* const* d_in, const int* in_sizes, int n_in,
                              void* d_out, int out_size) {
    const float* feat     = (const float*)d_in[0];
    const int*   ei       = (const int*)d_in[1];
    const float* ew       = (const float*)d_in[2];
    const float* rel_w    = (const float*)d_in[3];
    const float* rel_b    = (const float*)d_in[4];
    const float* gate_w   = (const float*)d_in[5];
    const float* gate_b   = (const float*)d_in[6];
    const float* la_w1    = (const float*)d_in[7];
    const float* la_b1    = (const float*)d_in[8];
    const float* la_w2    = (const float*)d_in[9];
    const float* la_b2    = (const float*)d_in[10];
    const float* pred_w   = (const float*)d_in[11];
    const float* pred_b   = (const float*)d_in[12];
    const float* att_bias = (const float*)d_in[13];
    const float* view_pref= (const float*)d_in[14];
    const float* va_w1    = (const float*)d_in[15];
    const float* va_b1    = (const float*)d_in[16];
    const float* va_w2    = (const float*)d_in[17];
    const float* va_b2    = (const float*)d_in[18];
    const float* ft_w     = (const float*)d_in[19];
    const float* ft_b     = (const float*)d_in[20];
    const float* sl_w     = (const float*)d_in[21];
    const float* sl_b     = (const float*)d_in[22];
    const float* fus_w    = (const float*)d_in[23];
    const float* fus_b    = (const float*)d_in[24];
    const float* ln_g     = (const float*)d_in[25];
    const float* ln_beta  = (const float*)d_in[26];
    float* out = (float*)d_out;

    cudaFuncSetAttribute(k_node, cudaFuncAttributeMaxDynamicSharedMemorySize, SMEM_BYTES);
    cudaFuncSetAttribute(k_view, cudaFuncAttributeMaxDynamicSharedMemorySize, SMEM_BYTES);
    cudaFuncSetAttribute(k_final, cudaFuncAttributeMaxDynamicSharedMemorySize, SMEM_BYTES);

    int write_probs = (out_size >= NN * (OO + 2)) ? 1 : 0;
    float* probs = out + (size_t)NN * OO;

    k_zero<<<2048, 256>>>();
    k_prep<<<128, 128>>>(sl_w, sl_b, fus_w);
    k_node<<<NBLK, NT, SMEM_BYTES>>>(feat, la_w1, la_b1, la_w2, la_b2,
                                     pred_w, pred_b, att_bias,
                                     ft_w, ft_b, ei, ew, probs, write_probs);
    k_view<<<dim3(NBLK, VV), NT, SMEM_BYTES>>>(rel_w, rel_b, gate_w, gate_b,
                                               view_pref, va_w1, va_b1, va_w2, va_b2);
    k_final<<<NBLK, NT, SMEM_BYTES>>>(fus_w + DD * OO, fus_b, ln_g, ln_beta, out);
}

// round 13
// speedup vs baseline: 1.1027x; 1.1027x over previous
#include <cuda_runtime.h>
#include <math.h>

#define NN 100000
#define DD 128
#define OO 128
#define VV 3
#define EE 400000
#define RT 132
#define NBLK 782
#define NT 256
#define TILEF (128 * RT)
#define WQF 8192
#define SMEMF (TILEF + WQF + 160)
#define SMEM_BYTES (SMEMF * 4)

typedef unsigned long long u64;

// ---------------- device scratch ----------------
__device__ float g_X[VV * NN * DD];
__device__ float g_s[VV * NN];
__device__ float g_att[NN];
__device__ float g_sfus[NN * OO];
__device__ float g_trans[NN * OO];
__device__ float g_views[VV * NN * OO];
__device__ float g_vscore[VV * NN];
__device__ float g_wp[OO * OO];    // sl_w @ fus_top
__device__ float g_bp[OO];         // sl_b @ fus_top

// ---------------- f32x2 helpers ----------------
__device__ __forceinline__ u64 pack2(float x, float y) {
    u64 r; asm("mov.b64 %0, {%1,%2};" : "=l"(r) : "f"(x), "f"(y)); return r;
}
__device__ __forceinline__ float2 unpack2(u64 v) {
    float2 f; asm("mov.b64 {%0,%1}, %2;" : "=f"(f.x), "=f"(f.y) : "l"(v)); return f;
}
__device__ __forceinline__ u64 fma2(u64 a, u64 b, u64 c) {
    u64 d; asm("fma.rn.f32x2 %0, %1, %2, %3;" : "=l"(d) : "l"(a), "l"(b), "l"(c)); return d;
}
__device__ __forceinline__ float sigm(float x) { return 1.0f / (1.0f + expf(-x)); }
__device__ __forceinline__ int nodeOf(int ng, int j) { return 4 * ng + (j < 4 ? j : 60 + j); }

#define CPCOMMIT asm volatile("cp.async.commit_group;" ::: "memory")

__device__ __forceinline__ void cpa16(float* ds, const float* gs) {
    unsigned sa = (unsigned)__cvta_generic_to_shared(ds);
    asm volatile("cp.async.ca.shared.global [%0], [%1], 16;" :: "r"(sa), "l"(gs) : "memory");
}
__device__ __forceinline__ void prefQ(float* dst, const float* __restrict__ src, int t) {
#pragma unroll
    for (int i = 0; i < 4; i++) cpa16(dst + 4 * (t + 256 * i), src + 4 * (t + 256 * i));
}
__device__ __forceinline__ void gemm_pre(float* wq, const float* __restrict__ wsrc, int t) {
    prefQ(wq, wsrc, t); CPCOMMIT;
    prefQ(wq + 4096, wsrc + 4096, t); CPCOMMIT;
}

// ---------------- loaders ----------------
__device__ __forceinline__ void load_tileT(float* dst, const float* __restrict__ src,
                                           int nb, int t) {
    for (int idx = t; idx < 4096; idx += NT) {
        int nodeLow = idx & 31;
        int kq = (idx >> 5) & 31;
        int node = ((idx >> 10) << 5) + nodeLow;
        float4 val = make_float4(0.f, 0.f, 0.f, 0.f);
        if (nb + node < NN) val = ((const float4*)src)[(size_t)(nb + node) * 32 + kq];
        dst[(4 * kq + 0) * RT + node] = val.x;
        dst[(4 * kq + 1) * RT + node] = val.y;
        dst[(4 * kq + 2) * RT + node] = val.z;
        dst[(4 * kq + 3) * RT + node] = val.w;
    }
}
__device__ __forceinline__ void load_la(float* wb, const float* __restrict__ la_w1,
                                        int half, int t) {
    for (int i = t; i < 2048; i += NT) {
        int d = i >> 5, col4 = i & 31;
        int c = col4 >> 4, h4 = col4 & 15;
        ((float4*)wb)[d * 32 + col4] =
            ((const float4*)la_w1)[(size_t)c * 2048 + (d + 64 * half) * 16 + h4];
    }
}

// ---------------- 8x8 register-tiled GEMM core ----------------
template <int KK, int WS>
__device__ __forceinline__ void mmTile(const float* __restrict__ aT,
                                       const float* __restrict__ wp, u64* acc) {
#pragma unroll 4
    for (int k = 0; k < KK; k++) {
        float4 x = *(const float4*)(aT);
        float4 y = *(const float4*)(aT + 64);
        float4 u = *(const float4*)(wp);
        float4 v = *(const float4*)(wp + 4);
        aT += RT; wp += WS;
        u64 p0 = pack2(x.x, x.y), p1 = pack2(x.z, x.w);
        u64 p2 = pack2(y.x, y.y), p3 = pack2(y.z, y.w);
        float wv[8] = {u.x, u.y, u.z, u.w, v.x, v.y, v.z, v.w};
#pragma unroll
        for (int n = 0; n < 8; n++) {
            u64 ws = pack2(wv[n], wv[n]);
            acc[n]      = fma2(p0, ws, acc[n]);
            acc[8 + n]  = fma2(p1, ws, acc[8 + n]);
            acc[16 + n] = fma2(p2, ws, acc[16 + n]);
            acc[24 + n] = fma2(p3, ws, acc[24 + n]);
        }
    }
}

// pipelined 128-k GEMM; gemm_pre must be in flight. Ends with __syncthreads().
__device__ __forceinline__ void gemm128p(const float* sfT, const float* __restrict__ wsrc,
                                         float* wq, int t, int og, int ng, u64* acc) {
#pragma unroll
    for (int c = 0; c < 4; c++) {
        if (c < 3) { asm volatile("cp.async.wait_group 1;" ::: "memory"); }
        else       { asm volatile("cp.async.wait_group 0;" ::: "memory"); }
        __syncthreads();
        mmTile<32, 128>(sfT + 32 * c * RT + 4 * ng, wq + (c & 1) * 4096 + 8 * og, acc);
        __syncthreads();
        if (c < 2) { prefQ(wq + (c & 1) * 4096, wsrc + (c + 2) * 4096, t); CPCOMMIT; }
    }
}

__device__ __forceinline__ void initB(u64* acc, const float* __restrict__ bias, int og) {
    float4 b0 = *(const float4*)(bias + 8 * og);
    float4 b1 = *(const float4*)(bias + 8 * og + 4);
    float bv[8] = {b0.x, b0.y, b0.z, b0.w, b1.x, b1.y, b1.z, b1.w};
#pragma unroll
    for (int n = 0; n < 8; n++) {
        u64 p = pack2(bv[n], bv[n]);
        acc[n] = p; acc[8 + n] = p; acc[16 + n] = p; acc[24 + n] = p;
    }
}

__device__ __forceinline__ void storeT(float* tile, int og, int ng, const u64* acc) {
    float* b = tile + 4 * ng;
#pragma unroll
    for (int n = 0; n < 8; n++) {
        float2 a0 = unpack2(acc[n]), a1 = unpack2(acc[8 + n]);
        float2 a2 = unpack2(acc[16 + n]), a3 = unpack2(acc[24 + n]);
        float* row = b + (8 * og + n) * RT;
        *(float4*)(row)      = make_float4(a0.x, a0.y, a1.x, a1.y);
        *(float4*)(row + 64) = make_float4(a2.x, a2.y, a3.x, a3.y);
    }
}

__device__ __forceinline__ void storeG(float* g, int nb, int og, int ng, const u64* acc) {
#pragma unroll
    for (int mp = 0; mp < 4; mp++) {
        int b = 4 * ng + (mp >> 1) * 64 + 2 * (mp & 1);
        int n0 = nb + b, n1 = n0 + 1;
        float2 c[8];
#pragma unroll
        for (int n = 0; n < 8; n++) c[n] = unpack2(acc[8 * mp + n]);
        if (n0 < NN) {
            float* p = g + (size_t)n0 * OO + 8 * og;
            *(float4*)p       = make_float4(c[0].x, c[1].x, c[2].x, c[3].x);
            *(float4*)(p + 4) = make_float4(c[4].x, c[5].x, c[6].x, c[7].x);
        }
        if (n1 < NN) {
            float* p = g + (size_t)n1 * OO + 8 * og;
            *(float4*)p       = make_float4(c[0].y, c[1].y, c[2].y, c[3].y);
            *(float4*)(p + 4) = make_float4(c[4].y, c[5].y, c[6].y, c[7].y);
        }
    }
}

// one scatter chunk (phase p of 3): warp-independent, no syncs
__device__ __forceinline__ void scatter_chunk(const float* __restrict__ feat,
                                              const int* __restrict__ ei,
                                              const float* __restrict__ ew,
                                              int t, int p) {
    const int lane = t & 31;
    for (int gw = blockIdx.x * 8 + (t >> 5) + p * NBLK * 8; gw < VV * EE;
         gw += NBLK * 24) {
        int v = gw / EE;
        int e = gw - v * EE;
        int src = ei[(size_t)v * 2 * EE + e];
        int dst = ei[(size_t)v * 2 * EE + EE + e];
        float w = ew[(size_t)v * EE + e];
        float4 m = ((const float4*)feat)[(size_t)src * 32 + lane];
        float* X = g_X + ((size_t)v * NN + dst) * DD + lane * 4;
        asm volatile("red.global.add.v4.f32 [%0], {%1,%2,%3,%4};"
                     :: "l"(X), "f"(m.x * w), "f"(m.y * w), "f"(m.z * w), "f"(m.w * w)
                     : "memory");
        if (lane == 0) atomicAdd(&g_s[(size_t)v * NN + dst], w);
    }
}

// =====================================================================
__global__ void k_zero() {
    size_t tid = (size_t)blockIdx.x * blockDim.x + threadIdx.x;
    size_t stride = (size_t)gridDim.x * blockDim.x;
    float4 z = make_float4(0.f, 0.f, 0.f, 0.f);
    float4* X = (float4*)g_X;
    size_t nx = (size_t)VV * NN * DD / 4;
    for (size_t i = tid; i < nx; i += stride) X[i] = z;
    float4* S = (float4*)g_s;
    for (size_t i = tid; i < VV * NN / 4; i += stride) S[i] = z;
}

// =====================================================================
__global__ void __launch_bounds__(128) k_prep(const float* __restrict__ sl_w,
                                              const float* __restrict__ sl_b,
                                              const float* __restrict__ fus_w) {
    __shared__ float row[128];
    const int i = blockIdx.x, j = threadIdx.x;
    row[j] = sl_w[i * 128 + j];
    __syncthreads();
    float acc = 0.f;
#pragma unroll 8
    for (int k = 0; k < 128; k++) acc += row[k] * __ldg(&fus_w[k * 128 + j]);
    g_wp[i * 128 + j] = acc;
    if (i == 0) {
        float accb = 0.f;
#pragma unroll 8
        for (int k = 0; k < 128; k++) accb += __ldg(&sl_b[k]) * __ldg(&fus_w[k * 128 + j]);
        g_bp[j] = accb;
    }
}

// =====================================================================
// K1: LA attention, trans, sfus' + interleaved edge scatter
// =====================================================================
__global__ void __launch_bounds__(NT, 2) k_node(
    const float* __restrict__ feat,
    const float* __restrict__ la_w1, const float* __restrict__ la_b1,
    const float* __restrict__ la_w2, const float* __restrict__ la_b2,
    const float* __restrict__ pred_w, const float* __restrict__ pred_b,
    const float* __restrict__ att_bias,
    const float* __restrict__ ft_w, const float* __restrict__ ft_b,
    const int* __restrict__ ei, const float* __restrict__ ew,
    float* __restrict__ probs, int write_probs) {
    extern __shared__ float sm[];
    float* sfT = sm;
    float* wq  = sm + TILEF;
    float* pwd = sm + TILEF + WQF;
    const int t = threadIdx.x, nb = blockIdx.x * 128;
    const int og = t & 15, ng = t >> 4;

    load_tileT(sfT, feat, nb, t);
    load_la(wq, la_w1, 0, t);
    if (t < 128) pwd[t] = __ldg(&pred_w[2 * t]) - __ldg(&pred_w[2 * t + 1]);
    __syncthreads();

    // ---- label-aware attention ----
    {
        u64 acc[32];
        initB(acc, la_b1, og);
        mmTile<64, 128>(sfT + 4 * ng, wq + 8 * og, acc);
        __syncthreads();
        load_la(wq, la_w1, 1, t);
        __syncthreads();
        mmTile<64, 128>(sfT + 64 * RT + 4 * ng, wq + 8 * og, acc);
        __syncthreads();                 // wq readers retired
        gemm_pre(wq, ft_w, t);           // prefetch ft_w behind LA epilogue

        u64 lgd[4] = {0, 0, 0, 0};
        const float* ap = sfT + 8 * og * RT + 4 * ng;
#pragma unroll
        for (int kk = 0; kk < 8; kk++) {
            float pw = pwd[8 * og + kk];
            u64 pws = pack2(pw, pw);
            float4 x = *(const float4*)(ap);
            float4 y = *(const float4*)(ap + 64);
            ap += RT;
            lgd[0] = fma2(pack2(x.x, x.y), pws, lgd[0]);
            lgd[1] = fma2(pack2(x.z, x.w), pws, lgd[1]);
            lgd[2] = fma2(pack2(y.x, y.y), pws, lgd[2]);
            lgd[3] = fma2(pack2(y.z, y.w), pws, lgd[3]);
        }
        float lg[8];
#pragma unroll
        for (int mp = 0; mp < 4; mp++) {
            float2 f = unpack2(lgd[mp]);
            lg[2 * mp] = f.x; lg[2 * mp + 1] = f.y;
        }
#pragma unroll
        for (int s = 1; s < 16; s <<= 1)
#pragma unroll
            for (int j = 0; j < 8; j++) lg[j] += __shfl_xor_sync(0xffffffffu, lg[j], s);

        float dt[8];
        {
            u64 dp[4] = {0, 0, 0, 0};
#pragma unroll
            for (int n = 0; n < 8; n++) {
                float wvn = la_w2[8 * og + n];
                u64 ws = pack2(wvn, wvn);
#pragma unroll
                for (int mp = 0; mp < 4; mp++) {
                    float2 a = unpack2(acc[8 * mp + n]);
                    dp[mp] = fma2(pack2(fmaxf(a.x, 0.f), fmaxf(a.y, 0.f)), ws, dp[mp]);
                }
            }
#pragma unroll
            for (int mp = 0; mp < 4; mp++) {
                float2 f = unpack2(dp[mp]);
                dt[2 * mp] = f.x; dt[2 * mp + 1] = f.y;
            }
#pragma unroll
            for (int s = 1; s < 8; s <<= 1)
#pragma unroll
                for (int j = 0; j < 8; j++) dt[j] += __shfl_xor_sync(0xffffffffu, dt[j], s);
        }
        const int c = og >> 3;
        const float b2 = la_b2[c];
        const float ab = att_bias[0];
        const float pbd = pred_b[0] - pred_b[1];
#pragma unroll
        for (int j = 0; j < 8; j++) {
            float sc = sigm(dt[j] + b2);
            float so = __shfl_xor_sync(0xffffffffu, sc, 8);
            float p0 = sigm(lg[j] + pbd);
            float pown = (c == 0) ? p0 : 1.f - p0;
            float att = sc * pown + so * (1.f - pown) + ab;
            int node = nb + nodeOf(ng, j);
            if (og == 0 && node < NN) {
                g_att[node] = att;
                if (write_probs) {
                    probs[(size_t)node * 2]     = p0;
                    probs[(size_t)node * 2 + 1] = 1.f - p0;
                }
            }
        }
    }
    scatter_chunk(feat, ei, ew, t, 0);   // overlap with ft_w prefetch in flight
    {   // trans = f@ft_w + ft_b
        u64 acc[32];
        initB(acc, ft_b, og);
        gemm128p(sfT, ft_w, wq, t, og, ng, acc);
        gemm_pre(wq, g_wp, t);
        storeG(g_trans, nb, og, ng, acc);
    }
    scatter_chunk(feat, ei, ew, t, 1);   // overlap with W' prefetch in flight
    {   // sfus = f@W' + b'
        u64 acc[32];
        initB(acc, g_bp, og);
        gemm128p(sfT, g_wp, wq, t, og, ng, acc);
        storeG(g_sfus, nb, og, ng, acc);
    }
    scatter_chunk(feat, ei, ew, t, 2);
}

// =====================================================================
// K3: per-view agg -> gate -> view/pe -> view-attention logits
// =====================================================================
__global__ void __launch_bounds__(NT, 2) k_view(
    const float* __restrict__ rel_w, const float* __restrict__ rel_b,
    const float* __restrict__ gate_w, const float* __restrict__ gate_b,
    const float* __restrict__ view_pref,
    const float* __restrict__ va_w1, const float* __restrict__ va_b1,
    const float* __restrict__ va_w2, const float* __restrict__ va_b2) {
    extern __shared__ float sm[];
    float* sfT = sm;
    float* wq  = sm + TILEF;
    const int t = threadIdx.x, nb = blockIdx.x * 128;
    const int v = blockIdx.y;
    const int og = t & 15, ng = t >> 4;

    gemm_pre(wq, rel_w + (size_t)v * DD * OO, t);
    load_tileT(sfT, g_X + (size_t)v * NN * DD, nb, t);
    __syncthreads();

    u64 sp[4];
#pragma unroll
    for (int mp = 0; mp < 4; mp++) {
        int b = 4 * ng + (mp >> 1) * 64 + 2 * (mp & 1);
        int i0 = min(nb + b, NN - 1), i1 = min(nb + b + 1, NN - 1);
        sp[mp] = pack2(g_s[v * NN + i0], g_s[v * NN + i1]);
    }
    {   // agg = X@rel_w + rel_b*s -> overwrite tile
        u64 acc[32];
        float4 b0 = *(const float4*)(rel_b + v * OO + 8 * og);
        float4 b1 = *(const float4*)(rel_b + v * OO + 8 * og + 4);
        float bv[8] = {b0.x, b0.y, b0.z, b0.w, b1.x, b1.y, b1.z, b1.w};
        u64 z = 0ull;
#pragma unroll
        for (int n = 0; n < 8; n++) {
            u64 rbs = pack2(bv[n], bv[n]);
#pragma unroll
            for (int mp = 0; mp < 4; mp++) acc[8 * mp + n] = fma2(rbs, sp[mp], z);
        }
        gemm128p(sfT, rel_w + (size_t)v * DD * OO, wq, t, og, ng, acc);  // ends synced
        gemm_pre(wq, gate_w + (size_t)v * OO * OO, t);
        storeT(sfT, og, ng, acc);        // tile := agg
        __syncthreads();
    }
    {   // gate logits; epilogue reads own agg cells then writes pe
        u64 acc[32];
        initB(acc, gate_b + v * OO, og);
        gemm128p(sfT, gate_w + (size_t)v * OO * OO, wq, t, og, ng, acc); // ends synced
        gemm_pre(wq, va_w1, t);
        float4 p0f = *(const float4*)(view_pref + v * OO + 8 * og);
        float4 p1f = *(const float4*)(view_pref + v * OO + 8 * og + 4);
        float pv[8] = {p0f.x, p0f.y, p0f.z, p0f.w, p1f.x, p1f.y, p1f.z, p1f.w};
#pragma unroll
        for (int n = 0; n < 8; n++) {
            const float* arow = sfT + (8 * og + n) * RT + 4 * ng;  // own cells
            float4 ga = *(const float4*)(arow);
            float4 gb = *(const float4*)(arow + 64);
            float2 a0 = unpack2(acc[n]),      a1 = unpack2(acc[8 + n]);
            float2 a2 = unpack2(acc[16 + n]), a3 = unpack2(acc[24 + n]);
            acc[n]      = pack2(sigm(a0.x) * ga.x, sigm(a0.y) * ga.y);
            acc[8 + n]  = pack2(sigm(a1.x) * ga.z, sigm(a1.y) * ga.w);
            acc[16 + n] = pack2(sigm(a2.x) * gb.x, sigm(a2.y) * gb.y);
            acc[24 + n] = pack2(sigm(a3.x) * gb.z, sigm(a3.y) * gb.w);
        }
        storeG(g_views + (size_t)v * NN * OO, nb, og, ng, acc);
        u64 z = 0ull;
#pragma unroll
        for (int n = 0; n < 8; n++) {
            u64 ps = pack2(pv[n], pv[n]);
#pragma unroll
            for (int mp = 0; mp < 4; mp++) acc[8 * mp + n] = fma2(acc[8 * mp + n], ps, z);
        }
        storeT(sfT, og, ng, acc);        // tile := pe (same cells this thread read)
    }
    asm volatile("cp.async.wait_group 0;" ::: "memory");
    __syncthreads();                     // pe tile + va weights visible
    {   // vh = relu(pe@va_w1+b1); vscore = vh·va_w2 + b2 (split-k over og bit3)
        const int ogp = og & 7, kh = og >> 3;
        u64 acc[32];
        if (kh == 0) {
            float4 b0 = *(const float4*)(va_b1 + 8 * ogp);
            float4 b1 = *(const float4*)(va_b1 + 8 * ogp + 4);
            float bv[8] = {b0.x, b0.y, b0.z, b0.w, b1.x, b1.y, b1.z, b1.w};
#pragma unroll
            for (int n = 0; n < 8; n++) {
                u64 p = pack2(bv[n], bv[n]);
                acc[n] = p; acc[8 + n] = p; acc[16 + n] = p; acc[24 + n] = p;
            }
        } else {
#pragma unroll
            for (int i = 0; i < 32; i++) acc[i] = 0ull;
        }
        mmTile<64, 64>(sfT + 64 * kh * RT + 4 * ng, wq + 4096 * kh + 8 * ogp, acc);
        float4 w0 = *(const float4*)(va_w2 + 8 * ogp);
        float4 w1 = *(const float4*)(va_w2 + 8 * ogp + 4);
        float wv[8] = {w0.x, w0.y, w0.z, w0.w, w1.x, w1.y, w1.z, w1.w};
        float dt[8] = {0.f, 0.f, 0.f, 0.f, 0.f, 0.f, 0.f, 0.f};
#pragma unroll
        for (int n = 0; n < 8; n++) {
            float wvn = wv[n];
#pragma unroll
            for (int mp = 0; mp < 4; mp++) {
                float2 a = unpack2(acc[8 * mp + n]);
                a.x += __shfl_xor_sync(0xffffffffu, a.x, 8);
                a.y += __shfl_xor_sync(0xffffffffu, a.y, 8);
                dt[2 * mp]     += fmaxf(a.x, 0.f) * wvn;
                dt[2 * mp + 1] += fmaxf(a.y, 0.f) * wvn;
            }
        }
#pragma unroll
        for (int s = 1; s < 8; s <<= 1)
#pragma unroll
            for (int j = 0; j < 8; j++) dt[j] += __shfl_xor_sync(0xffffffffu, dt[j], s);
        if (og == 0) {
            float vb = va_b2[0];
#pragma unroll
            for (int j = 0; j < 8; j++) {
                int node = nb + nodeOf(ng, j);
                if (node < NN) g_vscore[v * NN + node] = dt[j] + vb;
            }
        }
    }
}

// =====================================================================
// K4: softmax-combine, fuse, layernorm
// =====================================================================
__global__ void __launch_bounds__(NT, 2) k_final(
    const float* __restrict__ fus_w_bot, const float* __restrict__ fus_b,
    const float* __restrict__ ln_g, const float* __restrict__ ln_beta,
    float* __restrict__ out) {
    extern __shared__ float sm[];
    float* sfT = sm;
    float* wq  = sm + TILEF;
    const int t = threadIdx.x, nb = blockIdx.x * 128;
    const int og = t & 15, ng = t >> 4;

    gemm_pre(wq, fus_w_bot, t);
#pragma unroll
    for (int j = 0; j < 8; j++) {
        int col = nodeOf(ng, j);
        int ncl = min(nb + col, NN - 1);
        float s0 = g_vscore[ncl], s1 = g_vscore[NN + ncl], s2 = g_vscore[2 * NN + ncl];
        float mx = fmaxf(s0, fmaxf(s1, s2));
        float e0 = expf(s0 - mx), e1 = expf(s1 - mx), e2 = expf(s2 - mx);
        float att = g_att[ncl] / (e0 + e1 + e2);
        float p0 = e0 * att, p1 = e1 * att, p2 = e2 * att;
        const float* v0 = g_views + (size_t)ncl * OO + 8 * og;
        const float* v1 = g_views + ((size_t)NN + ncl) * OO + 8 * og;
        const float* v2 = g_views + ((size_t)2 * NN + ncl) * OO + 8 * og;
        float4 a0 = *(const float4*)v0, a1 = *(const float4*)(v0 + 4);
        float4 b0 = *(const float4*)v1, b1 = *(const float4*)(v1 + 4);
        float4 c0 = *(const float4*)v2, c1 = *(const float4*)(v2 + 4);
        float w[8];
        w[0] = a0.x * p0 + b0.x * p1 + c0.x * p2;
        w[1] = a0.y * p0 + b0.y * p1 + c0.y * p2;
        w[2] = a0.z * p0 + b0.z * p1 + c0.z * p2;
        w[3] = a0.w * p0 + b0.w * p1 + c0.w * p2;
        w[4] = a1.x * p0 + b1.x * p1 + c1.x * p2;
        w[5] = a1.y * p0 + b1.y * p1 + c1.y * p2;
        w[6] = a1.z * p0 + b1.z * p1 + c1.z * p2;
        w[7] = a1.w * p0 + b1.w * p1 + c1.w * p2;
#pragma unroll
        for (int n = 0; n < 8; n++) sfT[(8 * og + n) * RT + col] = w[n];
    }
    __syncthreads();

    u64 acc[32];
    {
        float4 f0 = *(const float4*)(fus_b + 8 * og);
        float4 f1 = *(const float4*)(fus_b + 8 * og + 4);
        float bv[8] = {f0.x, f0.y, f0.z, f0.w, f1.x, f1.y, f1.z, f1.w};
#pragma unroll
        for (int mp = 0; mp < 4; mp++) {
            int b = 4 * ng + (mp >> 1) * 64 + 2 * (mp & 1);
            int i0 = min(nb + b, NN - 1), i1 = min(nb + b + 1, NN - 1);
            const float* s0p = g_sfus + (size_t)i0 * OO + 8 * og;
            const float* s1p = g_sfus + (size_t)i1 * OO + 8 * og;
            float4 s00 = *(const float4*)s0p, s01 = *(const float4*)(s0p + 4);
            float4 s10 = *(const float4*)s1p, s11 = *(const float4*)(s1p + 4);
            float sa[8] = {s00.x, s00.y, s00.z, s00.w, s01.x, s01.y, s01.z, s01.w};
            float sb[8] = {s10.x, s10.y, s10.z, s10.w, s11.x, s11.y, s11.z, s11.w};
#pragma unroll
            for (int n = 0; n < 8; n++)
                acc[8 * mp + n] = pack2(sa[n] + bv[n], sb[n] + bv[n]);
        }
    }
    gemm128p(sfT, fus_w_bot, wq, t, og, ng, acc);

    float sums[8] = {0, 0, 0, 0, 0, 0, 0, 0};
    float sqs[8]  = {0, 0, 0, 0, 0, 0, 0, 0};
#pragma unroll
    for (int mp = 0; mp < 4; mp++) {
        int b = 4 * ng + (mp >> 1) * 64 + 2 * (mp & 1);
        int i0 = min(nb + b, NN - 1), i1 = min(nb + b + 1, NN - 1);
        const float* t0p = g_trans + (size_t)i0 * OO + 8 * og;
        const float* t1p = g_trans + (size_t)i1 * OO + 8 * og;
        float4 t00 = *(const float4*)t0p, t01 = *(const float4*)(t0p + 4);
        float4 t10 = *(const float4*)t1p, t11 = *(const float4*)(t1p + 4);
        float ta[8] = {t00.x, t00.y, t00.z, t00.w, t01.x, t01.y, t01.z, t01.w};
        float tb[8] = {t10.x, t10.y, t10.z, t10.w, t11.x, t11.y, t11.z, t11.w};
#pragma unroll
        for (int n = 0; n < 8; n++) {
            float2 a = unpack2(acc[8 * mp + n]);
            float o0 = fmaxf(a.x, 0.f) + ta[n];
            float o1 = fmaxf(a.y, 0.f) + tb[n];
            acc[8 * mp + n] = pack2(o0, o1);
            sums[2 * mp] += o0; sqs[2 * mp] += o0 * o0;
            sums[2 * mp + 1] += o1; sqs[2 * mp + 1] += o1 * o1;
        }
    }
#pragma unroll
    for (int s = 1; s < 16; s <<= 1)
#pragma unroll
        for (int j = 0; j < 8; j++) {
            sums[j] += __shfl_xor_sync(0xffffffffu, sums[j], s);
            sqs[j]  += __shfl_xor_sync(0xffffffffu, sqs[j], s);
        }
    float4 g0 = *(const float4*)(ln_g + 8 * og), g1 = *(const float4*)(ln_g + 8 * og + 4);
    float4 e0 = *(const float4*)(ln_beta + 8 * og), e1 = *(const float4*)(ln_beta + 8 * og + 4);
    float gv[8] = {g0.x, g0.y, g0.z, g0.w, g1.x, g1.y, g1.z, g1.w};
    float ev[8] = {e0.x, e0.y, e0.z, e0.w, e1.x, e1.y, e1.z, e1.w};
#pragma unroll
    for (int mp = 0; mp < 4; mp++) {
        int b = 4 * ng + (mp >> 1) * 64 + 2 * (mp & 1);
        int n0 = nb + b, n1 = n0 + 1;
        float mu0 = sums[2 * mp] * (1.f / 128.f);
        float mu1 = sums[2 * mp + 1] * (1.f / 128.f);
        float r0 = rsqrtf(sqs[2 * mp] * (1.f / 128.f) - mu0 * mu0 + 1e-5f);
        float r1 = rsqrtf(sqs[2 * mp + 1] * (1.f / 128.f) - mu1 * mu1 + 1e-5f);
        float2 c[8];
#pragma unroll
        for (int n = 0; n < 8; n++) c[n] = unpack2(acc[8 * mp + n]);
        if (n0 < NN) {
            float* p = out + (size_t)n0 * OO + 8 * og;
            float r[8];
#pragma unroll
            for (int n = 0; n < 8; n++) r[n] = (c[n].x - mu0) * r0 * gv[n] + ev[n];
            *(float4*)p       = make_float4(r[0], r[1], r[2], r[3]);
            *(float4*)(p + 4) = make_float4(r[4], r[5], r[6], r[7]);
        }
        if (n1 < NN) {
            float* p = out + (size_t)n1 * OO + 8 * og;
            float r[8];
#pragma unroll
            for (int n = 0; n < 8; n++) r[n] = (c[n].y - mu1) * r1 * gv[n] + ev[n];
            *(float4*)p       = make_float4(r[0], r[1], r[2], r[3]);
            *(float4*)(p + 4) = make_float4(r[4], r[5], r[6], r[7]);
        }
    }
}

// =====================================================================
extern "C" void kernel_launch(void* const* d_in, const int* in_sizes, int n_in,
                              void* d_out, int out_size) {
    const float* feat     = (const float*)d_in[0];
    const int*   ei       = (const int*)d_in[1];
    const float* ew       = (const float*)d_in[2];
    const float* rel_w    = (const float*)d_in[3];
    const float* rel_b    = (const float*)d_in[4];
    const float* gate_w   = (const float*)d_in[5];
    const float* gate_b   = (const float*)d_in[6];
    const float* la_w1    = (const float*)d_in[7];
    const float* la_b1    = (const float*)d_in[8];
    const float* la_w2    = (const float*)d_in[9];
    const float* la_b2    = (const float*)d_in[10];
    const float* pred_w   = (const float*)d_in[11];
    const float* pred_b   = (const float*)d_in[12];
    const float* att_bias = (const float*)d_in[13];
    const float* view_pref= (const float*)d_in[14];
    const float* va_w1    = (const float*)d_in[15];
    const float* va_b1    = (const float*)d_in[16];
    const float* va_w2    = (const float*)d_in[17];
    const float* va_b2    = (const float*)d_in[18];
    const float* ft_w     = (const float*)d_in[19];
    const float* ft_b     = (const float*)d_in[20];
    const float* sl_w     = (const float*)d_in[21];
    const float* sl_b     = (const float*)d_in[22];
    const float* fus_w    = (const float*)d_in[23];
    const float* fus_b    = (const float*)d_in[24];
    const float* ln_g     = (const float*)d_in[25];
    const float* ln_beta  = (const float*)d_in[26];
    float* out = (float*)d_out;

    cudaFuncSetAttribute(k_node, cudaFuncAttributeMaxDynamicSharedMemorySize, SMEM_BYTES);
    cudaFuncSetAttribute(k_view, cudaFuncAttributeMaxDynamicSharedMemorySize, SMEM_BYTES);
    cudaFuncSetAttribute(k_final, cudaFuncAttributeMaxDynamicSharedMemorySize, SMEM_BYTES);

    int write_probs = (out_size >= NN * (OO + 2)) ? 1 : 0;
    float* probs = out + (size_t)NN * OO;

    k_zero<<<2048, 256>>>();
    k_prep<<<128, 128>>>(sl_w, sl_b, fus_w);
    k_node<<<NBLK, NT, SMEM_BYTES>>>(feat, la_w1, la_b1, la_w2, la_b2,
                                     pred_w, pred_b, att_bias,
                                     ft_w, ft_b, ei, ew, probs, write_probs);
    k_view<<<dim3(NBLK, VV), NT, SMEM_BYTES>>>(rel_w, rel_b, gate_w, gate_b,
                                               view_pref, va_w1, va_b1, va_w2, va_b2);
    k_final<<<NBLK, NT, SMEM_BYTES>>>(fus_w + DD * OO, fus_b, ln_g, ln_beta, out);
}